// round 1
// baseline (speedup 1.0000x reference)
#include <cuda_runtime.h>
#include <cuda_bf16.h>
#include <math.h>

static constexpr int NN_  = 4900;
static constexpr int NB1  = 708;
static constexpr int NB2  = 4192;   // 4900 - 708
static constexpr int DIN  = 512;
static constexpr int DOUT = 256;
static constexpr long QK  = (long)NN_ * NN_;

#define CDIV(a,b) (((a)+(b)-1)/(b))

// ---------------- scratch (single static device buffer, offsets in floats) ----------------
static constexpr long O_RP = 0;                         // 4*256
static constexpr long O_HQ = O_RP + 4L*256;             // N*256
static constexpr long O_HK = O_HQ + (long)NN_*DOUT;
static constexpr long O_V  = O_HK + (long)NN_*DOUT;
static constexpr long O_H  = O_V  + (long)NN_*DOUT;
static constexpr long O_QG = O_H  + (long)NN_*DOUT;     // [2][4][N][64]
static constexpr long O_CT = O_QG + 2L*4*NN_*64;        // [512][708]
static constexpr long O_CB = O_CT + 512L*NB1;           // [512][4192]
static constexpr long O_BT = O_CB + 512L*NB2;           // [512][N]
static constexpr long O_BB = O_BT + 512L*NN_;           // [512][N]
static constexpr long O_VG = O_BB + 512L*NN_;           // [4][N][64]
static constexpr long O_M  = O_VG + 4L*NN_*64;          // [N][256]
static constexpr long O_HM = O_M  + (long)NN_*DOUT;     // [N][512]
static constexpr long O_BE = O_HM + (long)NN_*512;      // [N][256]
static constexpr long O_OU = O_BE + (long)NN_*DOUT;     // [N][256]
static constexpr long O_T  = O_OU + (long)NN_*DOUT;     // [N][256]
static constexpr long O_AL = O_T  + (long)NN_*DOUT;     // [4][N][N]
static constexpr long TOTAL_F = O_AL + 4L*QK;

__device__ float g_buf[TOTAL_F];

// ---------------- generic tiled fp32 GEMM: C = act( A0@B0 (+ A1@B1) + bias ) -------------
// All matrices row-major. Optional z-batching via per-operand z strides.
template<int BM,int BN,int BK,int TM,int TN>
__global__ void __launch_bounds__((BM/TM)*(BN/TN))
sgemm(const float* __restrict__ A0, int lda0, long zsA0,
      const float* __restrict__ B0, int ldb0, long zsB0, int K0,
      const float* __restrict__ A1, int lda1, long zsA1,
      const float* __restrict__ B1, int ldb1, long zsB1, int K1,
      const float* __restrict__ bias,
      float* __restrict__ C, int ldc, long zsC,
      int M, int N, int act)
{
    constexpr int THREADS = (BM/TM)*(BN/TN);
    __shared__ float As[BK][BM+4];
    __shared__ float Bs[BK][BN+4];

    const int z = blockIdx.z;
    A0 += (long)z * zsA0;
    B0 += (long)z * zsB0;
    if (A1) A1 += (long)z * zsA1;
    if (B1) B1 += (long)z * zsB1;
    C  += (long)z * zsC;

    const int bm = blockIdx.y * BM;
    const int bn = blockIdx.x * BN;
    const int tid = threadIdx.x;
    const int tx = tid % (BN/TN);
    const int ty = tid / (BN/TN);

    float acc[TM][TN];
    #pragma unroll
    for (int i=0;i<TM;i++)
        #pragma unroll
        for (int j=0;j<TN;j++) acc[i][j] = 0.f;

    for (int seg = 0; seg < 2; seg++) {
        const float* A = seg ? A1 : A0;
        const float* B = seg ? B1 : B0;
        const int K   = seg ? K1 : K0;
        const int lda = seg ? lda1 : lda0;
        const int ldb = seg ? ldb1 : ldb0;
        if (K <= 0) continue;

        for (int k0 = 0; k0 < K; k0 += BK) {
            #pragma unroll
            for (int i = tid; i < BM*BK; i += THREADS) {
                int m  = i / BK, kk = i % BK;
                int gm = bm + m, gk = k0 + kk;
                As[kk][m] = (gm < M && gk < K) ? A[(long)gm*lda + gk] : 0.f;
            }
            #pragma unroll
            for (int i = tid; i < BK*BN; i += THREADS) {
                int kk = i / BN, n = i % BN;
                int gk = k0 + kk, gn = bn + n;
                Bs[kk][n] = (gk < K && gn < N) ? B[(long)gk*ldb + gn] : 0.f;
            }
            __syncthreads();

            #pragma unroll
            for (int kk = 0; kk < BK; kk++) {
                float ar[TM], br[TN];
                #pragma unroll
                for (int i=0;i<TM;i++) ar[i] = As[kk][ty*TM+i];
                #pragma unroll
                for (int j=0;j<TN;j++) br[j] = Bs[kk][tx*TN+j];
                #pragma unroll
                for (int i=0;i<TM;i++)
                    #pragma unroll
                    for (int j=0;j<TN;j++) acc[i][j] += ar[i]*br[j];
            }
            __syncthreads();
        }
    }

    #pragma unroll
    for (int i=0;i<TM;i++) {
        int gm = bm + ty*TM + i;
        if (gm >= M) continue;
        #pragma unroll
        for (int j=0;j<TN;j++) {
            int gn = bn + tx*TN + j;
            if (gn >= N) continue;
            float v = acc[i][j] + (bias ? bias[gn] : 0.f);
            if (act == 1) v = 1.f / (1.f + __expf(-v));
            C[(long)gm*ldc + gn] = v;
        }
    }
}

// ---------------- gathers -----------------------------------------------------------------
// Qg[t][h][q][d]: modulated+head-gathered Q, scale 0.5 folded in.
__global__ void k_gatherQ(const float* __restrict__ hQ, const float* __restrict__ rp,
                          const int* __restrict__ flag, float* __restrict__ Qg)
{
    int idx = blockIdx.x*256 + threadIdx.x;
    if (idx >= 2*4*NN_*64) return;
    int d = idx & 63;
    int q = (idx >> 6) % NN_;
    int h = ((idx >> 6) / NN_) & 3;
    int t = idx / (4*NN_*64);
    int ridx = (flag[0] != 0) ? 1 : 0;
    int row, col, rsel;
    if (q < NB1) { row = h*177 + (q>>2);            col = ((q&3)<<6) + d; rsel = (t==0) ? ridx : 2; }
    else { int qq = q - NB1; row = NB1 + h*1048 + (qq>>2); col = ((qq&3)<<6) + d; rsel = (t==0) ? 2 : 3; }
    Qg[idx] = hQ[row*256 + col] * rp[rsel*256 + col] * 0.5f;
}

// CtopT[s*256+h*64+d][k], k<708 : gathered/modulated K (top rows). s=0 -> rp[ridx], s=1 -> rp[2]
__global__ void k_gatherCtop(const float* __restrict__ hK, const float* __restrict__ rp,
                             const int* __restrict__ flag, float* __restrict__ CT)
{
    int idx = blockIdx.x*256 + threadIdx.x;
    if (idx >= 512*NB1) return;
    int k = idx % NB1, rowi = idx / NB1;
    int s = rowi >> 8, hd = rowi & 255, h = hd >> 6, d = hd & 63;
    int ridx = (flag[0] != 0) ? 1 : 0;
    int rsel = (s==0) ? ridx : 2;
    int col = ((k&3)<<6) + d;
    CT[idx] = hK[(h*177 + (k>>2))*256 + col] * rp[rsel*256 + col];
}

// CbotT[s*256+h*64+d][k], k<4192 : gathered K (bottom rows). s=0 -> rp[2], s=1 -> rp[3]
__global__ void k_gatherCbot(const float* __restrict__ hK, const float* __restrict__ rp,
                             float* __restrict__ CB)
{
    int idx = blockIdx.x*256 + threadIdx.x;
    if (idx >= 512*NB2) return;
    int k = idx % NB2, rowi = idx / NB2;
    int s = rowi >> 8, hd = rowi & 255, h = hd >> 6, d = hd & 63;
    int rsel = (s==0) ? 2 : 3;
    int col = ((k&3)<<6) + d;
    CB[idx] = hK[(NB1 + h*1048 + (k>>2))*256 + col] * rp[rsel*256 + col];
}

// Vg[h][k][d] = V[h*1225 + k/4, (k%4)*64 + d]
__global__ void k_gatherV(const float* __restrict__ V, float* __restrict__ Vg)
{
    int idx = blockIdx.x*256 + threadIdx.x;
    if (idx >= 4*NN_*64) return;
    int d = idx & 63;
    int k = (idx >> 6) % NN_;
    int h = (idx >> 6) / NN_;
    Vg[idx] = V[(h*1225 + (k>>2))*256 + ((k&3)<<6) + d];
}

// ---------------- softmax over head axis (axis 0) -----------------------------------------
__global__ void k_softmax(float* __restrict__ al)
{
    long i = (long)blockIdx.x*256 + threadIdx.x;
    if (i >= QK) return;
    float a0 = al[i], a1 = al[i+QK], a2 = al[i+2*QK], a3 = al[i+3*QK];
    float mx = fmaxf(fmaxf(a0,a1), fmaxf(a2,a3));
    float e0 = __expf(a0-mx), e1 = __expf(a1-mx), e2 = __expf(a2-mx), e3 = __expf(a3-mx);
    float inv = 1.f / (e0+e1+e2+e3);
    al[i] = e0*inv; al[i+QK] = e1*inv; al[i+2*QK] = e2*inv; al[i+3*QK] = e3*inv;
}

// ---------------- layernorm helpers -------------------------------------------------------
__device__ __forceinline__ float blk_sum(float v)
{
    __shared__ float sw[8];
    #pragma unroll
    for (int o=16;o;o>>=1) v += __shfl_xor_sync(0xffffffffu, v, o);
    if ((threadIdx.x & 31) == 0) sw[threadIdx.x >> 5] = v;
    __syncthreads();
    float r = 0.f;
    if (threadIdx.x < 32) {
        r = (threadIdx.x < 8) ? sw[threadIdx.x] : 0.f;
        #pragma unroll
        for (int o=4;o;o>>=1) r += __shfl_xor_sync(0xffffffffu, r, o);
        if (threadIdx.x == 0) sw[0] = r;
    }
    __syncthreads();
    r = sw[0];
    __syncthreads();
    return r;
}

// m_ln = LN(relu(m)); pack HM = [H | m_ln]
__global__ void k_relu_ln_pack(const float* __restrict__ m, const float* __restrict__ H,
                               const float* __restrict__ gg, const float* __restrict__ bb,
                               float* __restrict__ HM)
{
    int row = blockIdx.x, tid = threadIdx.x;
    float x = fmaxf(m[row*256 + tid], 0.f);
    float s1 = blk_sum(x);
    float s2 = blk_sum(x*x);
    float mean = s1 * (1.f/256.f);
    float var  = s2 * (1.f/256.f) - mean*mean;
    float y = (x - mean) * rsqrtf(var + 1e-5f) * gg[tid] + bb[tid];
    HM[row*512 + 256 + tid] = y;
    HM[row*512 + tid]       = H[row*256 + tid];
}

__global__ void k_gate(const float* __restrict__ beta, const float* __restrict__ HM,
                       const float* __restrict__ H, float* __restrict__ out)
{
    int i = blockIdx.x*256 + threadIdx.x;
    if (i >= NN_*DOUT) return;
    int r = i >> 8, c = i & 255;
    float be = beta[i];
    float mv = HM[r*512 + 256 + c];
    out[i] = be*mv + (1.f - be)*H[i];
}

__global__ void k_ln_tanh(float* __restrict__ t, const float* __restrict__ gg,
                          const float* __restrict__ bb)
{
    int row = blockIdx.x, tid = threadIdx.x;
    float x = t[row*256 + tid];
    float s1 = blk_sum(x);
    float s2 = blk_sum(x*x);
    float mean = s1 * (1.f/256.f);
    float var  = s2 * (1.f/256.f) - mean*mean;
    t[row*256 + tid] = tanhf((x - mean) * rsqrtf(var + 1e-6f) * gg[tid] + bb[tid]);
}

// ---------------- host --------------------------------------------------------------------
extern "C" void kernel_launch(void* const* d_in, const int* in_sizes, int n_in,
                              void* d_out, int out_size)
{
    const float* feature = (const float*)d_in[0];
    const float* adj     = (const float*)d_in[1];
    const float* r       = (const float*)d_in[2];
    const float* Wq = (const float*)d_in[3];  const float* bq = (const float*)d_in[4];
    const float* Wk = (const float*)d_in[5];  const float* bk = (const float*)d_in[6];
    const float* Wv = (const float*)d_in[7];  const float* bv = (const float*)d_in[8];
    const float* Ww = (const float*)d_in[9];  const float* bw = (const float*)d_in[10];
    const float* Wr = (const float*)d_in[11]; const float* br = (const float*)d_in[12];
    const float* Wbeta = (const float*)d_in[13]; const float* bbeta = (const float*)d_in[14];
    const float* ln1g = (const float*)d_in[15]; const float* ln1b = (const float*)d_in[16];
    const float* w1 = (const float*)d_in[17]; const float* b1 = (const float*)d_in[18];
    const float* ln2g = (const float*)d_in[19]; const float* ln2b = (const float*)d_in[20];
    const float* w2 = (const float*)d_in[21];
    const int*   flag = (const int*)d_in[22];
    float* out = (float*)d_out;

    float* g = nullptr;
    cudaGetSymbolAddress((void**)&g, g_buf);
    float* rp   = g + O_RP;
    float* hQ   = g + O_HQ;
    float* hK   = g + O_HK;
    float* V    = g + O_V;
    float* H    = g + O_H;
    float* Qg   = g + O_QG;
    float* CT   = g + O_CT;
    float* CB   = g + O_CB;
    float* Bt   = g + O_BT;
    float* Bb   = g + O_BB;
    float* Vg   = g + O_VG;
    float* M_   = g + O_M;
    float* HM   = g + O_HM;
    float* BE   = g + O_BE;
    float* OU   = g + O_OU;
    float* T_   = g + O_T;
    float* AL   = g + O_AL;

    // 1) rp = r @ Wr + br                         [4,256] = [4,256]@[256,256]
    sgemm<64,64,16,4,4><<<dim3(4,1,1),256>>>(r,256,0, Wr,256,0,256,
        nullptr,0,0,nullptr,0,0,0, br, rp,256,0, 4,256,0);

    // 2) projections: hQ/hK/V/H = feature @ W* + b*    [4900,256]
    sgemm<64,64,16,4,4><<<dim3(4,77,1),256>>>(feature,512,0, Wq,256,0,512,
        nullptr,0,0,nullptr,0,0,0, bq, hQ,256,0, NN_,256,0);
    sgemm<64,64,16,4,4><<<dim3(4,77,1),256>>>(feature,512,0, Wk,256,0,512,
        nullptr,0,0,nullptr,0,0,0, bk, hK,256,0, NN_,256,0);
    sgemm<64,64,16,4,4><<<dim3(4,77,1),256>>>(feature,512,0, Wv,256,0,512,
        nullptr,0,0,nullptr,0,0,0, bv, V,256,0, NN_,256,0);
    sgemm<64,64,16,4,4><<<dim3(4,77,1),256>>>(feature,512,0, Ww,256,0,512,
        nullptr,0,0,nullptr,0,0,0, bw, H,256,0, NN_,256,0);

    // 3) gathers
    k_gatherQ  <<<CDIV(2*4*NN_*64,256),256>>>(hQ, rp, flag, Qg);
    k_gatherCtop<<<CDIV(512*NB1,256),256>>>(hK, rp, flag, CT);
    k_gatherCbot<<<CDIV(512*NB2,256),256>>>(hK, rp, CB);
    k_gatherV  <<<CDIV(4*NN_*64,256),256>>>(V, Vg);

    // 4) B-build: Bt = CT @ adj[0:708,:]   Bb = CB @ adj[708:,:]      [512,4900]
    sgemm<128,128,8,8,8><<<dim3(39,4,1),256>>>(CT,NB1,0, adj,NN_,0,NB1,
        nullptr,0,0,nullptr,0,0,0, nullptr, Bt,NN_,0, 512,NN_,0);
    sgemm<128,128,8,8,8><<<dim3(39,4,1),256>>>(CB,NB2,0, adj + (long)NB1*NN_,NN_,0,NB2,
        nullptr,0,0,nullptr,0,0,0, nullptr, Bb,NN_,0, 512,NN_,0);

    // 5) alpha[h] = Qg[0][h] @ Bt[boff+h*64] + Qg[1][h] @ Bb[boff+h*64]   (z = head)
    //    q-block 1 (rows 0..707, boff=0)
    sgemm<128,128,8,8,8><<<dim3(39,6,4),256>>>(
        Qg,            64, (long)NN_*64,  Bt,             NN_, 64L*NN_, 64,
        Qg+4L*NN_*64,  64, (long)NN_*64,  Bb,             NN_, 64L*NN_, 64,
        nullptr, AL, NN_, QK, NB1, NN_, 0);
    //    q-block 2 (rows 708.., boff=256)
    sgemm<128,128,8,8,8><<<dim3(39,33,4),256>>>(
        Qg + (long)NB1*64,           64, (long)NN_*64,  Bt + 256L*NN_, NN_, 64L*NN_, 64,
        Qg + 4L*NN_*64 + (long)NB1*64,64, (long)NN_*64, Bb + 256L*NN_, NN_, 64L*NN_, 64,
        nullptr, AL + (long)NB1*NN_, NN_, QK, NB2, NN_, 0);

    // 6) softmax over heads at each (q,k)
    k_softmax<<<(int)CDIV(QK,256),256>>>(AL);

    // 7) m[h] = w[h] @ Vg[h]  -> written directly into [N,256] layout (col offset h*64 via zsC)
    sgemm<128,64,8,8,4><<<dim3(1,39,4),256>>>(
        AL, NN_, QK,  Vg, 64, (long)NN_*64, NN_,
        nullptr,0,0, nullptr,0,0,0, nullptr, M_, 256, 64, NN_, 64, 0);

    // 8) m_ln = LN(relu(m)); HM = [H | m_ln]
    k_relu_ln_pack<<<NN_,256>>>(M_, H, ln1g, ln1b, HM);

    // 9) beta = sigmoid(HM @ Wbeta + bbeta)
    sgemm<64,64,16,4,4><<<dim3(4,77,1),256>>>(HM,512,0, Wbeta,256,0,512,
        nullptr,0,0,nullptr,0,0,0, bbeta, BE,256,0, NN_,256,1);

    // 10) out = beta*m_ln + (1-beta)*H
    k_gate<<<CDIV(NN_*DOUT,256),256>>>(BE, HM, H, OU);

    // 11) t = out @ w1 + b1
    sgemm<64,64,16,4,4><<<dim3(4,77,1),256>>>(OU,256,0, w1,256,0,256,
        nullptr,0,0,nullptr,0,0,0, b1, T_,256,0, NN_,256,0);

    // 12) t = tanh(LN(t))
    k_ln_tanh<<<NN_,256>>>(T_, ln2g, ln2b);

    // 13) final = t @ w2 -> d_out
    sgemm<64,64,16,4,4><<<dim3(4,77,1),256>>>(T_,256,0, w2,256,0,256,
        nullptr,0,0,nullptr,0,0,0, nullptr, out,256,0, NN_,256,0);
}